// round 7
// baseline (speedup 1.0000x reference)
#include <cuda_runtime.h>
#include <cuda_bf16.h>
#include <math.h>
#include <stdint.h>

// Problem constants
#define BDIM   2
#define VDIM   162
#define SDIM   4096
#define VS     (VDIM * SDIM)        // 663552
#define ODIM   32
#define KCH    5
#define F1     16
#define F2     32
#define NROWS  648                  // 4 * 162 stacked (k, v) rows
#define NPAD2  768                  // 6 m-tiles of 128
#define KPAD2  176                  // 11 k-chunks of 16
#define NKC    11
#define KFMAX  160
#define MAXELEM ((size_t)BDIM * ODIM * VS)

// Dynamic smem map for cheb_fused (bytes)
#define SM_BHI  0                   // 11 * 4096 = 45056
#define SM_BLO  45056               // 45056
#define SM_A    90112               // 2 bufs * (4096 hi + 4096 lo) = 16384
#define SM_TOT  106496

typedef unsigned long long ULL;
typedef unsigned short u16;

// Scratch
__device__ float g_y [BDIM * ODIM * VS];
__device__ float g_sum[ODIM];
__device__ float g_sumsq[ODIM];
__device__ float g_scale[ODIM];
__device__ float g_shift[ODIM];
__device__ float g_Tm[4 * VDIM * VDIM];
__device__ __align__(16) __nv_bfloat16 g_Thi[NPAD2 * KPAD2];
__device__ __align__(16) __nv_bfloat16 g_Tlo[NPAD2 * KPAD2];
__device__ __align__(16) __nv_bfloat16 g_bhi[(size_t)BDIM * F2 * KPAD2 * SDIM];
__device__ __align__(16) __nv_bfloat16 g_blo[(size_t)BDIM * F2 * KPAD2 * SDIM];
__device__ __align__(16) __nv_bfloat16 g_thi[(size_t)BDIM * F2 * NROWS * SDIM];
__device__ __align__(16) __nv_bfloat16 g_tlo[(size_t)BDIM * F2 * NROWS * SDIM];

// ---------------- helpers ---------------------------------------------------
__device__ __forceinline__ uint32_t smem_u32(const void* p) {
    uint32_t a;
    asm("{ .reg .u64 t; cvta.to.shared.u64 t, %1; cvt.u32.u64 %0, t; }" : "=r"(a) : "l"(p));
    return a;
}
__device__ __forceinline__ void cpa16(uint32_t s, const void* g) {
    asm volatile("cp.async.cg.shared.global [%0], [%1], 16;" :: "r"(s), "l"(g));
}
#define CP_COMMIT() asm volatile("cp.async.commit_group;" ::: "memory")
#define CP_WAIT(n)  asm volatile("cp.async.wait_group %0;" :: "n"(n) : "memory")

__device__ __forceinline__ void ldsm_x4(uint32_t* r, uint32_t a) {
    asm volatile("ldmatrix.sync.aligned.m8n8.x4.shared.b16 {%0,%1,%2,%3}, [%4];"
        : "=r"(r[0]), "=r"(r[1]), "=r"(r[2]), "=r"(r[3]) : "r"(a));
}
__device__ __forceinline__ void ldsm_x4t(uint32_t* r, uint32_t a) {
    asm volatile("ldmatrix.sync.aligned.m8n8.x4.trans.shared.b16 {%0,%1,%2,%3}, [%4];"
        : "=r"(r[0]), "=r"(r[1]), "=r"(r[2]), "=r"(r[3]) : "r"(a));
}
__device__ __forceinline__ void mma_bf16(float* c, const uint32_t* a, const uint32_t* b) {
    asm volatile("mma.sync.aligned.m16n8k16.row.col.f32.bf16.bf16.f32 "
        "{%0,%1,%2,%3}, {%4,%5,%6,%7}, {%8,%9}, {%0,%1,%2,%3};"
        : "+f"(c[0]), "+f"(c[1]), "+f"(c[2]), "+f"(c[3])
        : "r"(a[0]), "r"(a[1]), "r"(a[2]), "r"(a[3]), "r"(b[0]), "r"(b[1]));
}
__device__ __forceinline__ u16 bfu(__nv_bfloat16 h) { return *(u16*)&h; }

// ---------------- Chebyshev matrix precompute ------------------------------
__global__ void tmat_copy(const float* __restrict__ lap) {
    int i = blockIdx.x * blockDim.x + threadIdx.x;
    if (i < VDIM * VDIM) g_Tm[i] = lap[i];
}
__global__ void tmat_step(const float* __restrict__ lap, int kdst) {
    __shared__ float lrow[VDIM];
    int u = blockIdx.x, v = threadIdx.x;
    if (v < VDIM) lrow[v] = lap[u * VDIM + v];
    __syncthreads();
    if (v >= VDIM) return;
    const float* P = g_Tm + (kdst - 1) * VDIM * VDIM;
    float acc = 0.f;
    for (int w = 0; w < VDIM; w++) acc += lrow[w] * P[w * VDIM + v];
    float q = (kdst == 1) ? ((u == v) ? 1.f : 0.f)
                          : g_Tm[(kdst - 2) * VDIM * VDIM + u * VDIM + v];
    g_Tm[kdst * VDIM * VDIM + u * VDIM + v] = 2.f * acc - q;
}
__global__ void pack_T_mma() {
    int i = blockIdx.x * blockDim.x + threadIdx.x;
    if (i >= NPAD2 * KPAD2) return;
    int m = i / KPAD2, u = i % KPAD2;
    float val = 0.f;
    if (m < NROWS && u < VDIM) {
        int kc = (m >= 486) ? 3 : (m >= 324) ? 2 : (m >= 162) ? 1 : 0;
        int v = m - kc * VDIM;
        val = g_Tm[kc * VDIM * VDIM + v * VDIM + u];
    }
    __nv_bfloat16 hi = __float2bfloat16(val);
    __nv_bfloat16 lo = __float2bfloat16(val - __bfloat162float(hi));
    g_Thi[i] = hi; g_Tlo[i] = lo;
}

// ---------------- fused Chebyshev GEMM --------------------------------------
// Per block (s0, slice): convert fp32 src tile (+opt BN/ReLU) -> smem B
// (hi/lo, swizzled, K resident) + write hi/lo planes to g_bhi/g_blo;
// then loop 6 m-tiles streaming A chunks, 3-term bf16 MMA, emit t rows.
__global__ __launch_bounds__(256) void cheb_fused(
    const float* __restrict__ ext, int useY, int useBn)
{
    extern __shared__ unsigned char sm[];
    const uint32_t sb = smem_u32(sm);
    const int tid = threadIdx.x, lane = tid & 31, wid = tid >> 5;
    const int warpM = wid & 1, warpN = wid >> 1;    // 2 x 4 warps
    const int s0 = blockIdx.x * 128;
    const int slice = blockIdx.y;

    const float* src = (useY ? g_y : ext) + (size_t)slice * VS;
    float bsc = 1.f, bsh = 0.f;
    if (useBn) { int ch = slice & (ODIM - 1); bsc = g_scale[ch]; bsh = g_shift[ch]; }

    // ---- build resident B (and persist hi/lo planes for combine k=0 rows)
    for (int t = tid; t < KPAD2 * 16; t += 256) {
        int k = t >> 4, seg = t & 15;
        float f[8];
#pragma unroll
        for (int j = 0; j < 8; j++) f[j] = 0.f;
        if (k < VDIM) {
            const float* p = src + (size_t)k * SDIM + s0 + seg * 8;
            float4 a = *(const float4*)p;
            float4 b = *(const float4*)(p + 4);
            f[0]=a.x; f[1]=a.y; f[2]=a.z; f[3]=a.w;
            f[4]=b.x; f[5]=b.y; f[6]=b.z; f[7]=b.w;
            if (useBn)
#pragma unroll
                for (int j = 0; j < 8; j++) f[j] = fmaxf(fmaf(f[j], bsc, bsh), 0.f);
        }
        u16 hi[8], lo[8];
#pragma unroll
        for (int j = 0; j < 8; j++) {
            __nv_bfloat16 h = __float2bfloat16(f[j]);
            __nv_bfloat16 l = __float2bfloat16(f[j] - __bfloat162float(h));
            hi[j] = bfu(h); lo[j] = bfu(l);
        }
        uint4 hv = make_uint4((uint32_t)hi[0] | ((uint32_t)hi[1] << 16),
                              (uint32_t)hi[2] | ((uint32_t)hi[3] << 16),
                              (uint32_t)hi[4] | ((uint32_t)hi[5] << 16),
                              (uint32_t)hi[6] | ((uint32_t)hi[7] << 16));
        uint4 lv = make_uint4((uint32_t)lo[0] | ((uint32_t)lo[1] << 16),
                              (uint32_t)lo[2] | ((uint32_t)lo[3] << 16),
                              (uint32_t)lo[4] | ((uint32_t)lo[5] << 16),
                              (uint32_t)lo[6] | ((uint32_t)lo[7] << 16));
        int kw = k & 15;
        uint32_t addr = (uint32_t)((k >> 4) * 4096 + kw * 256 + ((seg ^ (kw & 7)) << 4));
        *(uint4*)(sm + SM_BHI + addr) = hv;
        *(uint4*)(sm + SM_BLO + addr) = lv;
        if (k < VDIM) {
            size_t off = ((size_t)slice * KPAD2 + k) * SDIM + s0 + seg * 8;
            *(uint4*)&g_bhi[off] = hv;
            *(uint4*)&g_blo[off] = lv;
        }
    }

    // ---- A chunk streaming (double buffered)
    const int cam = tid >> 1, cakh = tid & 1;
    const uint32_t caAdst = (uint32_t)(cam * 32 + ((cakh ^ ((cam >> 2) & 1)) << 4));
    auto prefA = [&](int g) {
        int mt = g / NKC, kc = g - mt * NKC;
        uint32_t st = sb + SM_A + (g & 1) * 8192;
        size_t aoff = (size_t)(mt * 128 + cam) * KPAD2 + kc * 16 + cakh * 8;
        cpa16(st + caAdst,        g_Thi + aoff);
        cpa16(st + 4096 + caAdst, g_Tlo + aoff);
        CP_COMMIT();
    };

    const int aRow = ((lane >> 3) & 1) * 8 + (lane & 7);
    const int aKh  = lane >> 4;
    const int bK   = ((lane >> 3) & 1) * 8 + (lane & 7);
    const int bNbO = lane >> 4;

    float acc[4][4][4];
#pragma unroll
    for (int i = 0; i < 4; i++)
#pragma unroll
        for (int j = 0; j < 4; j++)
#pragma unroll
            for (int q = 0; q < 4; q++) acc[i][j][q] = 0.f;

    prefA(0);
    __syncthreads();    // B smem visible; A(0) committed

    const size_t sliceBase = (size_t)slice * NROWS * SDIM;

    for (int g = 0; g < 6 * NKC; g++) {
        const int mt = g / NKC, kc = g - mt * NKC;
        if (g + 1 < 6 * NKC) { prefA(g + 1); CP_WAIT(1); } else { CP_WAIT(0); }
        __syncthreads();

        uint32_t stA = sb + SM_A + (g & 1) * 8192;
        uint32_t Ah[4][4], Al[4][4], Bhf[4][2], Blf[4][2];
#pragma unroll
        for (int f = 0; f < 4; f++) {
            int m = warpM * 64 + f * 16 + aRow;
            uint32_t ad = (uint32_t)(m * 32 + ((aKh ^ ((m >> 2) & 1)) << 4));
            ldsm_x4(Ah[f], stA + ad);
            ldsm_x4(Al[f], stA + 4096 + ad);
        }
        uint32_t bBase = (uint32_t)(kc * 4096);
#pragma unroll
        for (int p = 0; p < 2; p++) {
            int nb = warpN * 4 + p * 2 + bNbO;
            uint32_t bd = bBase + (uint32_t)(bK * 256 + ((nb ^ (bK & 7)) << 4));
            uint32_t r[4];
            ldsm_x4t(r, sb + SM_BHI + bd);
            Bhf[p*2][0] = r[0]; Bhf[p*2][1] = r[1];
            Bhf[p*2+1][0] = r[2]; Bhf[p*2+1][1] = r[3];
            ldsm_x4t(r, sb + SM_BLO + bd);
            Blf[p*2][0] = r[0]; Blf[p*2][1] = r[1];
            Blf[p*2+1][0] = r[2]; Blf[p*2+1][1] = r[3];
        }
#pragma unroll
        for (int mf = 0; mf < 4; mf++)
#pragma unroll
            for (int nf = 0; nf < 4; nf++) {
                mma_bf16(acc[mf][nf], Ah[mf], Bhf[nf]);
                mma_bf16(acc[mf][nf], Ah[mf], Blf[nf]);
                mma_bf16(acc[mf][nf], Al[mf], Bhf[nf]);
            }

        if (kc == NKC - 1) {
            // epilogue for this m-tile; then clear accumulators
            const int m0g = mt * 128;
#pragma unroll
            for (int mf = 0; mf < 4; mf++) {
                int mbase = m0g + warpM * 64 + mf * 16 + (lane >> 2);
#pragma unroll
                for (int half = 0; half < 2; half++) {
                    int n = mbase + half * 8;
                    if (n < NROWS) {
                        size_t off = sliceBase + (size_t)n * SDIM
                                   + s0 + warpN * 32 + (lane & 3) * 2;
#pragma unroll
                        for (int nf = 0; nf < 4; nf++) {
                            float2 val = half ? make_float2(acc[mf][nf][2], acc[mf][nf][3])
                                              : make_float2(acc[mf][nf][0], acc[mf][nf][1]);
                            __nv_bfloat16 h0 = __float2bfloat16(val.x);
                            __nv_bfloat16 h1 = __float2bfloat16(val.y);
                            __nv_bfloat16 l0 = __float2bfloat16(val.x - __bfloat162float(h0));
                            __nv_bfloat16 l1 = __float2bfloat16(val.y - __bfloat162float(h1));
                            *(ushort2*)&g_thi[off + nf * 8] = make_ushort2(bfu(h0), bfu(h1));
                            *(ushort2*)&g_tlo[off + nf * 8] = make_ushort2(bfu(l0), bfu(l1));
                        }
                    }
                }
            }
#pragma unroll
            for (int i = 0; i < 4; i++)
#pragma unroll
                for (int j = 0; j < 4; j++)
#pragma unroll
                    for (int q = 0; q < 4; q++) acc[i][j][q] = 0.f;
        }
        __syncthreads();
    }
}

// ---------------- combine via mma.sync (unchanged from R6) -----------------
__global__ __launch_bounds__(256) void combine_mma(
    const float* __restrict__ w, const float* __restrict__ bias, int Fin)
{
    __shared__ ULL pHi[KFMAX], pLo[KFMAX];
    __shared__ __align__(16) u16 Ahw[10 * 512];
    __shared__ __align__(16) u16 Alw[10 * 512];
    __shared__ __align__(128) u16 Bb[2][2][2048];
    __shared__ float s_sum[ODIM], s_sq[ODIM];

    const int tid = threadIdx.x, lane = tid & 31, wid = tid >> 5;
    const int warpM = wid & 1, warpN = wid >> 1;
    const int KF = KCH * Fin, NKCc = KF / 16;
    const int n0 = blockIdx.x * 128;
    const int v = n0 >> 12, sOff = n0 & 4095;
    const int b = blockIdx.y;

    for (int i = tid; i < KF; i += 256) {
        int k = i / Fin, f = i % Fin, slice = b * Fin + f;
        if (k == 0) {
            size_t o = ((size_t)slice * KPAD2 + v) * SDIM + sOff;
            pHi[i] = (ULL)(g_bhi + o); pLo[i] = (ULL)(g_blo + o);
        } else {
            size_t o = ((size_t)slice * NROWS + (size_t)(k - 1) * VDIM + v) * SDIM + sOff;
            pHi[i] = (ULL)(g_thi + o); pLo[i] = (ULL)(g_tlo + o);
        }
    }
    for (int i = tid; i < KF * 32; i += 256) {
        int kf = i >> 5, o = i & 31;
        float val = w[i];
        __nv_bfloat16 h = __float2bfloat16(val);
        __nv_bfloat16 l = __float2bfloat16(val - __bfloat162float(h));
        int c = kf >> 4, kw = kf & 15, kh = kw >> 3, kb = kw & 7;
        int addr = c * 512 + o * 16 + ((kh ^ ((o >> 2) & 1)) << 3) + kb;
        Ahw[addr] = bfu(h); Alw[addr] = bfu(l);
    }
    if (tid < ODIM) { s_sum[tid] = 0.f; s_sq[tid] = 0.f; }
    __syncthreads();

    const uint32_t aHib = smem_u32(Ahw), aLob = smem_u32(Alw);
    const uint32_t bB[2][2] = {
        {smem_u32(Bb[0][0]), smem_u32(Bb[0][1])},
        {smem_u32(Bb[1][0]), smem_u32(Bb[1][1])}
    };

    const int row = tid >> 4, seg = tid & 15;
    const uint32_t bdst = (uint32_t)(row * 256 + ((seg ^ (row & 7)) << 4));

    auto prefetch = [&](int c) {
        int kf = c * 16 + row;
        cpa16(bB[c & 1][0] + bdst, (const u16*)pHi[kf] + seg * 8);
        cpa16(bB[c & 1][1] + bdst, (const u16*)pLo[kf] + seg * 8);
        CP_COMMIT();
    };

    const int aRow = ((lane >> 3) & 1) * 8 + (lane & 7);
    const int aKh  = lane >> 4;
    const int bK   = ((lane >> 3) & 1) * 8 + (lane & 7);
    const int bNbO = lane >> 4;

    float acc[4][4];
#pragma unroll
    for (int i = 0; i < 4; i++)
#pragma unroll
        for (int q = 0; q < 4; q++) acc[i][q] = 0.f;

    prefetch(0);
    for (int c = 0; c < NKCc; c++) {
        if (c + 1 < NKCc) { prefetch(c + 1); CP_WAIT(1); } else { CP_WAIT(0); }
        __syncthreads();

        int ar = warpM * 16 + aRow;
        uint32_t aad = (uint32_t)(c * 1024 + ar * 32 + ((aKh ^ ((ar >> 2) & 1)) << 4));
        uint32_t Af[4], Alf_[4];
        ldsm_x4(Af,  aHib + aad);
        ldsm_x4(Alf_, aLob + aad);

        uint32_t Bhf[4][2], Blf[4][2];
#pragma unroll
        for (int p = 0; p < 2; p++) {
            int nb = warpN * 4 + p * 2 + bNbO;
            uint32_t bd = (uint32_t)(bK * 256 + ((nb ^ (bK & 7)) << 4));
            uint32_t r[4];
            ldsm_x4t(r, bB[c & 1][0] + bd);
            Bhf[p*2][0] = r[0]; Bhf[p*2][1] = r[1];
            Bhf[p*2+1][0] = r[2]; Bhf[p*2+1][1] = r[3];
            ldsm_x4t(r, bB[c & 1][1] + bd);
            Blf[p*2][0] = r[0]; Blf[p*2][1] = r[1];
            Blf[p*2+1][0] = r[2]; Blf[p*2+1][1] = r[3];
        }
#pragma unroll
        for (int nf = 0; nf < 4; nf++) {
            mma_bf16(acc[nf], Af,   Bhf[nf]);
            mma_bf16(acc[nf], Af,   Blf[nf]);
            mma_bf16(acc[nf], Alf_, Bhf[nf]);
        }
        __syncthreads();
    }

    const int orow = warpM * 16 + (lane >> 2);
#pragma unroll
    for (int half = 0; half < 2; half++) {
        int o = orow + half * 8;
        float bo = bias[o];
        float* yo = g_y + ((size_t)(b * ODIM + o)) * VS + n0 + warpN * 32 + (lane & 3) * 2;
        float ps = 0.f, pq = 0.f;
#pragma unroll
        for (int nf = 0; nf < 4; nf++) {
            float2 val = half ? make_float2(acc[nf][2], acc[nf][3])
                              : make_float2(acc[nf][0], acc[nf][1]);
            val.x += bo; val.y += bo;
            *(float2*)(yo + nf * 8) = val;
            ps += val.x + val.y;
            pq += val.x * val.x + val.y * val.y;
        }
        atomicAdd(&s_sum[o], ps);
        atomicAdd(&s_sq[o],  pq);
    }
    __syncthreads();
    if (tid < ODIM) {
        atomicAdd(&g_sum[tid],   s_sum[tid]);
        atomicAdd(&g_sumsq[tid], s_sq[tid]);
    }
}

__global__ void zero_stats() {
    int i = threadIdx.x;
    if (i < ODIM) { g_sum[i] = 0.f; g_sumsq[i] = 0.f; }
}

__global__ void finalize_stats(const float* __restrict__ gamma,
                               const float* __restrict__ beta, float ncnt)
{
    int o = threadIdx.x;
    if (o < ODIM) {
        float mean = g_sum[o] / ncnt;
        float var  = g_sumsq[o] / ncnt - mean * mean;
        float sc   = gamma[o] * rsqrtf(var + 1e-5f);
        g_scale[o] = sc;
        g_shift[o] = beta[o] - mean * sc;
    }
}

__global__ void norm_relu(float* __restrict__ out)
{
    const size_t total4 = MAXELEM / 4;
    const size_t stride = (size_t)gridDim.x * blockDim.x;
    for (size_t i = (size_t)blockIdx.x * blockDim.x + threadIdx.x;
         i < total4; i += stride) {
        size_t e = i * 4;
        int o = (int)((e / VS) % ODIM);
        float sc = g_scale[o], sh = g_shift[o];
        float4 v = ((const float4*)g_y)[i];
        v.x = fmaxf(fmaf(v.x, sc, sh), 0.f);
        v.y = fmaxf(fmaf(v.y, sc, sh), 0.f);
        v.z = fmaxf(fmaf(v.z, sc, sh), 0.f);
        v.w = fmaxf(fmaf(v.w, sc, sh), 0.f);
        ((float4*)out)[i] = v;
    }
}

// ---------------------------------------------------------------------------
extern "C" void kernel_launch(void* const* d_in, const int* in_sizes, int n_in,
                              void* d_out, int out_size)
{
    const float* x   = (const float*)d_in[0];
    const float* lap = (const float*)d_in[1];
    const float* w1  = (const float*)d_in[2];
    const float* b1  = (const float*)d_in[3];
    const float* g1  = (const float*)d_in[4];
    const float* be1 = (const float*)d_in[5];
    const float* w2  = (const float*)d_in[6];
    const float* b2  = (const float*)d_in[7];
    const float* g2  = (const float*)d_in[8];
    const float* be2 = (const float*)d_in[9];
    float* out = (float*)d_out;
    (void)in_sizes; (void)n_in; (void)out_size;

    cudaFuncSetAttribute(cheb_fused, cudaFuncAttributeMaxDynamicSharedMemorySize, SM_TOT);

    const float ncnt = (float)((size_t)BDIM * VS);
    dim3 gcomb(VS / 128, BDIM);

    tmat_copy<<<(VDIM * VDIM + 255) / 256, 256>>>(lap);
    tmat_step<<<VDIM, 192>>>(lap, 1);
    tmat_step<<<VDIM, 192>>>(lap, 2);
    tmat_step<<<VDIM, 192>>>(lap, 3);
    pack_T_mma<<<(NPAD2 * KPAD2 + 255) / 256, 256>>>();

    // ---- Layer 1 ----
    cheb_fused<<<dim3(SDIM / 128, BDIM * F1), 256, SM_TOT>>>(x, 0, 0);
    zero_stats<<<1, 32>>>();
    combine_mma<<<gcomb, 256>>>(w1, b1, F1);
    finalize_stats<<<1, 32>>>(g1, be1, ncnt);

    // ---- Layer 2 ----
    cheb_fused<<<dim3(SDIM / 128, BDIM * F2), 256, SM_TOT>>>(nullptr, 1, 1);
    zero_stats<<<1, 32>>>();
    combine_mma<<<gcomb, 256>>>(w2, b2, F2);
    finalize_stats<<<1, 32>>>(g2, be2, ncnt);
    norm_relu<<<2048, 256>>>(out);
}